// round 9
// baseline (speedup 1.0000x reference)
#include <cuda_runtime.h>
#include <cuda_bf16.h>
#include <math.h>
#include <stdint.h>

#define BB 16
#define LL 4096
#define PD 512
#define HH 256
#define NB 2048            // rank buckets
#define NCH 8              // fp32 K chunks of 64

// ---------------------------------------------------------------------------
// scratch (static device memory — no allocations allowed)
// ---------------------------------------------------------------------------
__device__ int   g_keptlist[BB * LL];
__device__ int   g_lenkeep[BB];
__device__ float g_fsemb[BB * HH];
// per chunk c: [Bhi 256x64 | Blo 256x64] flat = 32768 bf16; 8 chunks = 512 KB
__device__ __align__(1024) __nv_bfloat16 g_Bs[8 * 32768];

// ---------------------------------------------------------------------------
// PTX helpers (plain sm_80/90 PTX — no 'a'-gated instructions)
// ---------------------------------------------------------------------------
__device__ __forceinline__ uint32_t smem_u32(const void* p) {
    uint32_t a;
    asm("{ .reg .u64 t; cvta.to.shared.u64 t, %1; cvt.u32.u64 %0, t; }" : "=r"(a) : "l"(p));
    return a;
}
__device__ __forceinline__ void cp16(uint32_t s, const void* g) {
    asm volatile("cp.async.cg.shared.global [%0], [%1], 16;" :: "r"(s), "l"(g));
}
#define CP_COMMIT() asm volatile("cp.async.commit_group;" ::: "memory")

__device__ __forceinline__ void ldsm4(uint32_t* r, uint32_t a) {
    asm volatile("ldmatrix.sync.aligned.m8n8.x4.shared.b16 {%0,%1,%2,%3}, [%4];"
                 : "=r"(r[0]), "=r"(r[1]), "=r"(r[2]), "=r"(r[3]) : "r"(a));
}
__device__ __forceinline__ void mma16816(float* d, const uint32_t* a,
                                         uint32_t b0, uint32_t b1) {
    asm volatile(
        "mma.sync.aligned.m16n8k16.row.col.f32.bf16.bf16.f32 "
        "{%0,%1,%2,%3}, {%4,%5,%6,%7}, {%8,%9}, {%0,%1,%2,%3};"
        : "+f"(d[0]), "+f"(d[1]), "+f"(d[2]), "+f"(d[3])
        : "r"(a[0]), "r"(a[1]), "r"(a[2]), "r"(a[3]), "r"(b0), "r"(b1));
}

// ---------------------------------------------------------------------------
// block-wide exclusive scan over one int per thread (1024 threads)
// ---------------------------------------------------------------------------
__device__ __forceinline__ int block_exscan(int v, int* wsum) {
    int lane = threadIdx.x & 31, wid = threadIdx.x >> 5;
    int inc = v;
#pragma unroll
    for (int d = 1; d < 32; d <<= 1) {
        int u = __shfl_up_sync(0xffffffffu, inc, d);
        if (lane >= d) inc += u;
    }
    if (lane == 31) wsum[wid] = inc;
    __syncthreads();
    if (wid == 0) {
        int s = wsum[lane];
#pragma unroll
        for (int d = 1; d < 32; d <<= 1) {
            int u = __shfl_up_sync(0xffffffffu, s, d);
            if (lane >= d) s += u;
        }
        wsum[lane] = s;
    }
    __syncthreads();
    return ((wid > 0) ? wsum[wid - 1] : 0) + (inc - v);
}

// ---------------------------------------------------------------------------
// k_prep: fused setup + bucket-rank + scan + timestep MLP.
// One block (1024 thr) per batch row.
// ---------------------------------------------------------------------------
__global__ void __launch_bounds__(1024, 1)
k_prep(const int* __restrict__ sids, const int* __restrict__ eff_lens,
       const float* __restrict__ noise, float* __restrict__ out,
       const float* __restrict__ fs,
       const float* __restrict__ w1, const float* __restrict__ b1,
       const float* __restrict__ w2, const float* __restrict__ b2) {
    __shared__ unsigned long long s_keys[LL];   // 32 KB (reused for fs MLP)
    __shared__ int s_hist[NB + 1];
    __shared__ int s_wsum[32];
    __shared__ int s_ns;

    int b = blockIdx.x;
    int t = threadIdx.x;
    int lane = t & 31, wid = t >> 5;
    int eff = eff_lens[b];
    int base = t * 4;

    s_hist[t] = 0;
    if (t < NB + 1 - 1024) s_hist[1024 + t] = 0;
    if (t == 0) { s_hist[NB] = 0; s_ns = 0; }

    int4  sd4 = *(const int4*)  &sids [b * LL + base];
    float4 nz4 = *(const float4*)&noise[b * LL + base];
    int sm1 = (base >= 1) ? sids[b * LL + base - 1] : -1;
    int sm2 = (base >= 2) ? sids[b * LL + base - 2] : -1;
    __syncthreads();

    int   sd[6] = {sm2, sm1, sd4.x, sd4.y, sd4.z, sd4.w};
    float nz[4] = {nz4.x, nz4.y, nz4.z, nz4.w};

    unsigned long long key[4];
    int bid[4], slot[4];
    int nseg = 0;
#pragma unroll
    for (int i = 0; i < 4; i++) {
        int l = base + i;
        bool valid = l < eff;
        bool seg = valid && (sd[i + 2] != sd[i + 1]);
        bool fst = valid && (l >= 1) && (sd[i + 1] != sd[i]);
        nseg += seg ? 1 : 0;
        float v = (seg || fst) ? 0.0f : nz[i];
        unsigned int bits = __float_as_uint(v);
        key[i] = ((unsigned long long)bits << 12) | (unsigned)l;
        bid[i] = min(NB - 1, (int)(v * (float)NB));
        if (valid) slot[i] = atomicAdd(&s_hist[bid[i]], 1);
    }
    {
        int v = nseg;
#pragma unroll
        for (int d = 16; d > 0; d >>= 1) v += __shfl_down_sync(0xffffffffu, v, d);
        if (lane == 0 && v) atomicAdd(&s_ns, v);
    }
    __syncthreads();

    int ns = s_ns;
    int lk = 2 * ns + (int)((float)(eff - 2 * ns) * 0.25f);

    int c0 = s_hist[2 * t], c1 = s_hist[2 * t + 1];
    int ex = block_exscan(c0 + c1, s_wsum);
    s_hist[2 * t] = ex;
    s_hist[2 * t + 1] = ex + c0;
    if (t == 1023) s_hist[NB] = ex + c0 + c1;
    __syncthreads();

#pragma unroll
    for (int i = 0; i < 4; i++) {
        int l = base + i;
        if (l < eff) s_keys[s_hist[bid[i]] + slot[i]] = key[i];
    }
    __syncthreads();

    int r[4];
    bool kept[4];
    int cnt = 0;
#pragma unroll
    for (int i = 0; i < 4; i++) {
        int l = base + i;
        if (l < eff) {
            int lo = s_hist[bid[i]], hi = s_hist[bid[i] + 1];
            int c = 0;
            for (int m = lo; m < hi; m++) c += (s_keys[m] < key[i]) ? 1 : 0;
            r[i] = lo + c;
        } else {
            r[i] = l;
        }
        kept[i] = (l < eff) && (r[i] < lk);
        cnt += kept[i] ? 1 : 0;
    }
    __syncthreads();

    int p = block_exscan(cnt, s_wsum);

    const size_t O1 = (size_t)BB * LL * HH;
    const size_t O2 = O1 + (size_t)BB * LL;
    const size_t O3 = O2 + (size_t)BB * LL;
    float* mae = out + O1 + (size_t)b * LL;
    float* rst = out + O2 + (size_t)b * LL;
    float* unm = out + O3 + (size_t)b * LL;

#pragma unroll
    for (int i = 0; i < 4; i++) {
        int l = base + i;
        mae[l] = (l < eff && !kept[i]) ? 1.0f : 0.0f;
        rst[l] = (float)(kept[i] ? p : r[i]);
        if (kept[i]) {
            g_keptlist[b * LL + p] = l;
            unm[p] = (float)sd[i + 2];
            p++;
        }
        if (l >= lk) unm[l] = -1.0f;
    }
    if (t == 0) g_lenkeep[b] = lk;

    // ================= timestep MLP tail (reuses s_keys smem) ===============
    __syncthreads();            // all prep reads of s_keys/s_hist done
    float* tf = (float*)s_keys;        // 256 floats
    float* h1 = tf + 256;              // 256 floats
    if (t < 128) {
        float fr = expf(-9.2103403719761836f * (float)t * (1.0f / 128.0f));
        float arg = fs[b] * fr;
        tf[t] = cosf(arg);
        tf[t + 128] = sinf(arg);
    }
    __syncthreads();

    // layer 1: 32 warps x 8 outputs, warp-per-output dot256
    {
        float tv[8];
#pragma unroll
        for (int i = 0; i < 8; i++) tv[i] = tf[lane * 8 + i];
#pragma unroll
        for (int j = 0; j < 8; j++) {
            int h = wid * 8 + j;
            float4 a0 = *(const float4*)&w1[h * 256 + lane * 8];
            float4 a1 = *(const float4*)&w1[h * 256 + lane * 8 + 4];
            float s = tv[0]*a0.x + tv[1]*a0.y + tv[2]*a0.z + tv[3]*a0.w
                    + tv[4]*a1.x + tv[5]*a1.y + tv[6]*a1.z + tv[7]*a1.w;
#pragma unroll
            for (int d = 16; d > 0; d >>= 1) s += __shfl_down_sync(0xffffffffu, s, d);
            if (lane == 0) { s += b1[h]; h1[h] = s / (1.0f + expf(-s)); }
        }
    }
    __syncthreads();

    // layer 2
    {
        float hv[8];
#pragma unroll
        for (int i = 0; i < 8; i++) hv[i] = h1[lane * 8 + i];
#pragma unroll
        for (int j = 0; j < 8; j++) {
            int h = wid * 8 + j;
            float4 a0 = *(const float4*)&w2[h * 256 + lane * 8];
            float4 a1 = *(const float4*)&w2[h * 256 + lane * 8 + 4];
            float s = hv[0]*a0.x + hv[1]*a0.y + hv[2]*a0.z + hv[3]*a0.w
                    + hv[4]*a1.x + hv[5]*a1.y + hv[6]*a1.z + hv[7]*a1.w;
#pragma unroll
            for (int d = 16; d > 0; d >>= 1) s += __shfl_down_sync(0xffffffffu, s, d);
            if (lane == 0) g_fsemb[b * 256 + h] = s + b2[h];
        }
    }
}

// ---------------------------------------------------------------------------
// k_convW: W fp32 -> per-chunk [Bhi | Blo] bf16.  16384 threads.
// ---------------------------------------------------------------------------
__global__ void k_convW(const float* __restrict__ W) {
    int gid = blockIdx.x * 256 + threadIdx.x;   // 16384
    int row = gid >> 6;          // 0..255
    int g   = gid & 63;          // col group of 8 f32
    int c   = g >> 3;            // chunk
    int cc  = (g & 7) * 8;       // col within chunk
    float4 v0 = *(const float4*)&W[(size_t)row * PD + g * 8];
    float4 v1 = *(const float4*)&W[(size_t)row * PD + g * 8 + 4];
    float a[8] = {v0.x, v0.y, v0.z, v0.w, v1.x, v1.y, v1.z, v1.w};
    __align__(16) __nv_bfloat16 oh[8], ol[8];
#pragma unroll
    for (int i = 0; i < 8; i++) {
        __nv_bfloat16 h = __float2bfloat16_rn(a[i]);
        oh[i] = h;
        ol[i] = __float2bfloat16_rn(a[i] - __bfloat162float(h));
    }
    *(uint4*)&g_Bs[c * 32768 + row * 64 + cc]         = *(const uint4*)oh;
    *(uint4*)&g_Bs[c * 32768 + 16384 + row * 64 + cc] = *(const uint4*)ol;
}

// ---------------------------------------------------------------------------
// k_gemm: fused convert + mma.sync bf16 3-term GEMM + tail zeroing.
// Block (512 thr, 16 warps) = (batch, M-tile 128).  N=256 whole.
// 8 fp32 K-chunks of 64 cols.  A gathered via direct LDG -> regs -> converted
// into double-buffered A'hi/lo smem inside the MMA region; B' via double-
// buffered cp.async.  ONE sync per chunk.
// SMEM from 128-aligned base AB:
//   0: sBF[256]f  1024: sKL[128]i
//   2048:  A' buf x2 (each: hi 16K @+0, lo 16K @+16384) = 64 KB
//   67584: B' buf x2 (each: hi 32K @+0, lo 32K @+32768) = 128 KB
// ---------------------------------------------------------------------------
#define SM_AP 2048
#define SM_BP 67584
#define SMEMSZ (198656 + 1024)

__global__ void __launch_bounds__(512, 1)
k_gemm(const float* __restrict__ patches,
       const float* __restrict__ bias, const float* __restrict__ pos,
       float* __restrict__ out_seq) {
    extern __shared__ char dsm[];
    int b  = blockIdx.y;
    int p0 = blockIdx.x * 128;
    int lk = g_lenkeep[b];
    int t = threadIdx.x;

    // ---- pure-zero blocks: whole tile is tail (block-uniform branch) ----
    if (p0 >= lk) {
        float4* dst = (float4*)&out_seq[((size_t)b * LL + p0) * HH];
        float4 z = make_float4(0.f, 0.f, 0.f, 0.f);
#pragma unroll
        for (int i = 0; i < 16; i++) dst[t + i * 512] = z;
        return;
    }

    uint32_t AB = (smem_u32(dsm) + 127u) & ~127u;
    char* ABp = dsm + (AB - smem_u32(dsm));
    float* sBF = (float*)(ABp);
    int*   sKL = (int*)(ABp + 1024);

    int lane = t & 31, wid = t >> 5;
    int wm = wid & 3, wn = wid >> 2;

    if (t < 256) sBF[t] = bias[t] + g_fsemb[b * HH + t];
    if (t < 128) {
        int p = p0 + t;
        sKL[t] = (p < lk) ? g_keptlist[b * LL + p] : 0;
    }
    __syncthreads();   // sKL needed for LDG addresses

    // ---- A LDG mapping: row = t>>2, 16 f32 at col (t&3)*16 ----
    int cvr = t >> 2;
    int cvc = t & 3;
    const float* aPtr = &patches[((size_t)b * LL + sKL[cvr]) * PD + cvc * 16];
    // A' store: hi 2 STS.128 at swizzled segs {cvc*2, cvc*2+1} ^ (row&7); lo same
    uint32_t aStBase = (uint32_t)(SM_AP + cvr * 128);
    uint32_t aSeg0 = (uint32_t)(((cvc * 2)     ^ (cvr & 7)) * 16);
    uint32_t aSeg1 = (uint32_t)(((cvc * 2 + 1) ^ (cvr & 7)) * 16);

    // ---- B' cp addresses: 4096 segs (512 rows x 8 segs) / 512 -> 8 ----
    uint32_t bDst[8];
    int bSrcOff[8];
#pragma unroll
    for (int i = 0; i < 8; i++) {
        int sid = t + i * 512;
        int r = sid >> 3, s = sid & 7;
        bDst[i] = AB + SM_BP + (uint32_t)(r * 128 + ((s ^ (r & 7)) * 16));
        bSrcOff[i] = r * 64 + s * 8;
    }

    // ---- ldmatrix address components ----
    uint32_t aRB[2], aXP[2];
#pragma unroll
    for (int mt = 0; mt < 2; mt++) {
        int rowA = wm * 32 + mt * 16 + (lane & 15);
        aRB[mt] = AB + SM_AP + (uint32_t)(rowA * 128);
        aXP[mt] = (uint32_t)((rowA & 7) << 4);
    }
    uint32_t aSG = (uint32_t)((lane >> 4) * 16);
    uint32_t bRB[4], bXP[4];
#pragma unroll
    for (int g = 0; g < 4; g++) {
        int rowB = wn * 64 + g * 16 + ((lane >> 4) << 3) + (lane & 7);
        bRB[g] = AB + SM_BP + (uint32_t)(rowB * 128);
        bXP[g] = (uint32_t)((rowB & 7) << 4);
    }
    uint32_t bSG = (uint32_t)(((lane >> 3) & 1) * 16);

    float acc[2][8][4];
#pragma unroll
    for (int mt = 0; mt < 2; mt++)
#pragma unroll
        for (int nt = 0; nt < 8; nt++)
#pragma unroll
            for (int i = 0; i < 4; i++) acc[mt][nt][i] = 0.f;

    float4 av[4];

    auto cp_B = [&](int c) {
        uint32_t bb = (uint32_t)(c & 1) * 65536u;
        const __nv_bfloat16* Bg = &g_Bs[c * 32768];
#pragma unroll
        for (int i = 0; i < 8; i++) cp16(bDst[i] + bb, Bg + bSrcOff[i]);
        CP_COMMIT();
    };
    auto ldg_A = [&](int c) {
#pragma unroll
        for (int i = 0; i < 4; i++)
            av[i] = __ldg((const float4*)(aPtr + c * 64 + i * 4));
    };
    auto conv_A = [&](int c) {
        uint32_t hi[8], lo[8];
#pragma unroll
        for (int i = 0; i < 4; i++) {
            float4 v = av[i];
            __nv_bfloat162 h01 = __float22bfloat162_rn(make_float2(v.x, v.y));
            __nv_bfloat162 h23 = __float22bfloat162_rn(make_float2(v.z, v.w));
            float2 hf01 = __bfloat1622float2(h01);
            float2 hf23 = __bfloat1622float2(h23);
            __nv_bfloat162 l01 = __float22bfloat162_rn(make_float2(v.x - hf01.x, v.y - hf01.y));
            __nv_bfloat162 l23 = __float22bfloat162_rn(make_float2(v.z - hf23.x, v.w - hf23.y));
            hi[i * 2]     = *(uint32_t*)&h01;
            hi[i * 2 + 1] = *(uint32_t*)&h23;
            lo[i * 2]     = *(uint32_t*)&l01;
            lo[i * 2 + 1] = *(uint32_t*)&l23;
        }
        uint32_t base = aStBase + (uint32_t)(c & 1) * 32768u;
        *(uint4*)(ABp + base + aSeg0)         = make_uint4(hi[0], hi[1], hi[2], hi[3]);
        *(uint4*)(ABp + base + aSeg1)         = make_uint4(hi[4], hi[5], hi[6], hi[7]);
        *(uint4*)(ABp + base + 16384 + aSeg0) = make_uint4(lo[0], lo[1], lo[2], lo[3]);
        *(uint4*)(ABp + base + 16384 + aSeg1) = make_uint4(lo[4], lo[5], lo[6], lo[7]);
    };

    // ---- prologue: B'(0) in flight; convert A(0) ----
    cp_B(0);
    ldg_A(0);
    conv_A(0);
    asm volatile("cp.async.wait_group 0;" ::: "memory");
    __syncthreads();

    for (int c = 0; c < NCH; c++) {
        uint32_t ab = (uint32_t)(c & 1) * 32768u;
        uint32_t bb = (uint32_t)(c & 1) * 65536u;
        if (c + 1 < NCH) { cp_B(c + 1); ldg_A(c + 1); }

        // ---- MMA: 4 k16 stages x 3 terms; convert(c+1) inserted mid-stream ----
#pragma unroll
        for (int s = 0; s < 4; s++) {
            uint32_t ah[2][4], al[2][4], bf[4][4];
            uint32_t so = (uint32_t)(s * 32);
#pragma unroll
            for (int mt = 0; mt < 2; mt++) {
                uint32_t off = (so + aSG) ^ aXP[mt];
                ldsm4(ah[mt], aRB[mt] + ab + off);
                ldsm4(al[mt], aRB[mt] + ab + 16384u + off);
            }
#pragma unroll
            for (int g = 0; g < 4; g++)
                ldsm4(bf[g], bRB[g] + bb + ((so + bSG) ^ bXP[g]));
#pragma unroll
            for (int mt = 0; mt < 2; mt++)
#pragma unroll
                for (int nt = 0; nt < 8; nt++)
                    mma16816(acc[mt][nt], ah[mt],
                             bf[nt >> 1][(nt & 1) * 2], bf[nt >> 1][(nt & 1) * 2 + 1]);
            if (s == 0 && c + 1 < NCH) conv_A(c + 1);   // overlaps tensor work
#pragma unroll
            for (int mt = 0; mt < 2; mt++)
#pragma unroll
                for (int nt = 0; nt < 8; nt++)
                    mma16816(acc[mt][nt], al[mt],
                             bf[nt >> 1][(nt & 1) * 2], bf[nt >> 1][(nt & 1) * 2 + 1]);
#pragma unroll
            for (int g = 0; g < 4; g++)  // Blo region = +32768
                ldsm4(bf[g], bRB[g] + bb + 32768u + ((so + bSG) ^ bXP[g]));
#pragma unroll
            for (int mt = 0; mt < 2; mt++)
#pragma unroll
                for (int nt = 0; nt < 8; nt++)
                    mma16816(acc[mt][nt], ah[mt],
                             bf[nt >> 1][(nt & 1) * 2], bf[nt >> 1][(nt & 1) * 2 + 1]);
        }
        asm volatile("cp.async.wait_group 0;" ::: "memory");
        __syncthreads();
    }

    // ---- epilogue: acc + bias + fsemb + pos -> out; tail rows -> 0 ----
#pragma unroll
    for (int mt = 0; mt < 2; mt++) {
        int rbase = wm * 32 + mt * 16 + (lane >> 2);
#pragma unroll
        for (int h = 0; h < 2; h++) {
            int rr = rbase + h * 8;
            int p = p0 + rr;
            int kl = sKL[rr];
            bool ok = p < lk;
            float* orow = &out_seq[(((size_t)b * LL) + p) * HH];
            const float* prow = &pos[(size_t)kl * HH];
#pragma unroll
            for (int nt = 0; nt < 8; nt++) {
                int col = wn * 64 + nt * 8 + (lane & 3) * 2;
                float2 v;
                if (ok) {
                    v.x = acc[mt][nt][h * 2 + 0] + sBF[col]     + prow[col];
                    v.y = acc[mt][nt][h * 2 + 1] + sBF[col + 1] + prow[col + 1];
                } else {
                    v.x = 0.f; v.y = 0.f;
                }
                *(float2*)&orow[col] = v;
            }
        }
    }
}

// ---------------------------------------------------------------------------
extern "C" void kernel_launch(void* const* d_in, const int* in_sizes, int n_in,
                              void* d_out, int out_size) {
    const float* patches = (const float*)d_in[0];
    const int*   sids    = (const int*)  d_in[1];
    const int*   eff     = (const int*)  d_in[2];
    const float* noise   = (const float*)d_in[3];
    const float* fs      = (const float*)d_in[4];
    const float* W       = (const float*)d_in[5];
    const float* bias    = (const float*)d_in[6];
    const float* pos     = (const float*)d_in[7];
    const float* w1      = (const float*)d_in[8];
    const float* b1      = (const float*)d_in[9];
    const float* w2      = (const float*)d_in[10];
    const float* b2      = (const float*)d_in[11];
    float* out = (float*)d_out;

    cudaFuncSetAttribute(k_gemm, cudaFuncAttributeMaxDynamicSharedMemorySize, SMEMSZ);

    k_prep<<<BB, 1024>>>(sids, eff, noise, out, fs, w1, b1, w2, b2);
    k_convW<<<64, 256>>>(W);
    k_gemm<<<dim3(32, BB), 512, SMEMSZ>>>(patches, bias, pos, out);

    (void)in_sizes; (void)n_in; (void)out_size;
}

// round 10
// speedup vs baseline: 1.1383x; 1.1383x over previous
#include <cuda_runtime.h>
#include <cuda_bf16.h>
#include <math.h>
#include <stdint.h>

#define BB 16
#define LL 4096
#define PD 512
#define HH 256
#define NB 2048            // rank buckets
#define NCH 8              // fp32 K chunks of 64

// ---------------------------------------------------------------------------
// scratch (static device memory — no allocations allowed)
// ---------------------------------------------------------------------------
__device__ int   g_keptlist[BB * LL];
__device__ int   g_lenkeep[BB];
__device__ float g_fsemb[BB * HH];
// per chunk c: [Bhi 256x64 | Blo 256x64] flat = 32768 bf16; 8 chunks = 512 KB
__device__ __align__(1024) __nv_bfloat16 g_Bs[8 * 32768];

// ---------------------------------------------------------------------------
// PTX helpers (plain sm_80/90 PTX — no 'a'-gated instructions)
// ---------------------------------------------------------------------------
__device__ __forceinline__ uint32_t smem_u32(const void* p) {
    uint32_t a;
    asm("{ .reg .u64 t; cvta.to.shared.u64 t, %1; cvt.u32.u64 %0, t; }" : "=r"(a) : "l"(p));
    return a;
}
__device__ __forceinline__ void cp16(uint32_t s, const void* g) {
    asm volatile("cp.async.cg.shared.global [%0], [%1], 16;" :: "r"(s), "l"(g));
}
#define CP_COMMIT() asm volatile("cp.async.commit_group;" ::: "memory")

__device__ __forceinline__ void ldsm4(uint32_t* r, uint32_t a) {
    asm volatile("ldmatrix.sync.aligned.m8n8.x4.shared.b16 {%0,%1,%2,%3}, [%4];"
                 : "=r"(r[0]), "=r"(r[1]), "=r"(r[2]), "=r"(r[3]) : "r"(a));
}
__device__ __forceinline__ void mma16816(float* d, const uint32_t* a,
                                         uint32_t b0, uint32_t b1) {
    asm volatile(
        "mma.sync.aligned.m16n8k16.row.col.f32.bf16.bf16.f32 "
        "{%0,%1,%2,%3}, {%4,%5,%6,%7}, {%8,%9}, {%0,%1,%2,%3};"
        : "+f"(d[0]), "+f"(d[1]), "+f"(d[2]), "+f"(d[3])
        : "r"(a[0]), "r"(a[1]), "r"(a[2]), "r"(a[3]), "r"(b0), "r"(b1));
}

// ---------------------------------------------------------------------------
// block-wide exclusive scan over one int per thread (1024 threads)
// ---------------------------------------------------------------------------
__device__ __forceinline__ int block_exscan(int v, int* wsum) {
    int lane = threadIdx.x & 31, wid = threadIdx.x >> 5;
    int inc = v;
#pragma unroll
    for (int d = 1; d < 32; d <<= 1) {
        int u = __shfl_up_sync(0xffffffffu, inc, d);
        if (lane >= d) inc += u;
    }
    if (lane == 31) wsum[wid] = inc;
    __syncthreads();
    if (wid == 0) {
        int s = wsum[lane];
#pragma unroll
        for (int d = 1; d < 32; d <<= 1) {
            int u = __shfl_up_sync(0xffffffffu, s, d);
            if (lane >= d) s += u;
        }
        wsum[lane] = s;
    }
    __syncthreads();
    return ((wid > 0) ? wsum[wid - 1] : 0) + (inc - v);
}

// ---------------------------------------------------------------------------
// k_front: role-dispatched front kernel, grid 48 x 1024 threads.
//   blocks  0..15 : prep (sort/rank/scan) for batch b = blockIdx.x
//   blocks 16..31 : timestep MLP (both layers) for b = blockIdx.x - 16
//   blocks 32..47 : W fp32 -> [Bhi|Blo] bf16 conversion (1/16 slice each)
// ---------------------------------------------------------------------------
__global__ void __launch_bounds__(1024, 1)
k_front(const int* __restrict__ sids, const int* __restrict__ eff_lens,
        const float* __restrict__ noise, float* __restrict__ out,
        const float* __restrict__ fs,
        const float* __restrict__ w1, const float* __restrict__ b1,
        const float* __restrict__ w2, const float* __restrict__ b2,
        const float* __restrict__ W) {
    __shared__ unsigned long long s_keys[LL];   // 32 KB (prep) / reused by fs
    __shared__ int s_hist[NB + 1];
    __shared__ int s_wsum[32];
    __shared__ int s_ns;

    int t = threadIdx.x;
    int lane = t & 31, wid = t >> 5;

    // ======================= role: convW (blocks 32..47) ====================
    if (blockIdx.x >= 32) {
        int gid = (blockIdx.x - 32) * 1024 + t;   // 16384 items
        int row = gid >> 6;          // 0..255
        int g   = gid & 63;          // col group of 8 f32
        int c   = g >> 3;            // chunk
        int cc  = (g & 7) * 8;       // col within chunk
        float4 v0 = *(const float4*)&W[(size_t)row * PD + g * 8];
        float4 v1 = *(const float4*)&W[(size_t)row * PD + g * 8 + 4];
        float a[8] = {v0.x, v0.y, v0.z, v0.w, v1.x, v1.y, v1.z, v1.w};
        __align__(16) __nv_bfloat16 oh[8], ol[8];
#pragma unroll
        for (int i = 0; i < 8; i++) {
            __nv_bfloat16 h = __float2bfloat16_rn(a[i]);
            oh[i] = h;
            ol[i] = __float2bfloat16_rn(a[i] - __bfloat162float(h));
        }
        *(uint4*)&g_Bs[c * 32768 + row * 64 + cc]         = *(const uint4*)oh;
        *(uint4*)&g_Bs[c * 32768 + 16384 + row * 64 + cc] = *(const uint4*)ol;
        return;
    }

    // ======================= role: fs MLP (blocks 16..31) ===================
    if (blockIdx.x >= 16) {
        int b = blockIdx.x - 16;
        float* tf = (float*)s_keys;        // 256 floats
        float* h1 = tf + 256;              // 256 floats
        if (t < 128) {
            float fr = expf(-9.2103403719761836f * (float)t * (1.0f / 128.0f));
            float arg = fs[b] * fr;
            tf[t] = cosf(arg);
            tf[t + 128] = sinf(arg);
        }
        __syncthreads();
        {   // layer 1: 32 warps x 8 outputs each
            float tv[8];
#pragma unroll
            for (int i = 0; i < 8; i++) tv[i] = tf[lane * 8 + i];
#pragma unroll
            for (int j = 0; j < 8; j++) {
                int h = wid * 8 + j;
                float4 a0 = *(const float4*)&w1[h * 256 + lane * 8];
                float4 a1 = *(const float4*)&w1[h * 256 + lane * 8 + 4];
                float s = tv[0]*a0.x + tv[1]*a0.y + tv[2]*a0.z + tv[3]*a0.w
                        + tv[4]*a1.x + tv[5]*a1.y + tv[6]*a1.z + tv[7]*a1.w;
#pragma unroll
                for (int d = 16; d > 0; d >>= 1) s += __shfl_down_sync(0xffffffffu, s, d);
                if (lane == 0) { s += b1[h]; h1[h] = s / (1.0f + expf(-s)); }
            }
        }
        __syncthreads();
        {   // layer 2
            float hv[8];
#pragma unroll
            for (int i = 0; i < 8; i++) hv[i] = h1[lane * 8 + i];
#pragma unroll
            for (int j = 0; j < 8; j++) {
                int h = wid * 8 + j;
                float4 a0 = *(const float4*)&w2[h * 256 + lane * 8];
                float4 a1 = *(const float4*)&w2[h * 256 + lane * 8 + 4];
                float s = hv[0]*a0.x + hv[1]*a0.y + hv[2]*a0.z + hv[3]*a0.w
                        + hv[4]*a1.x + hv[5]*a1.y + hv[6]*a1.z + hv[7]*a1.w;
#pragma unroll
                for (int d = 16; d > 0; d >>= 1) s += __shfl_down_sync(0xffffffffu, s, d);
                if (lane == 0) g_fsemb[b * 256 + h] = s + b2[h];
            }
        }
        return;
    }

    // ======================= role: prep (blocks 0..15) ======================
    int b = blockIdx.x;
    int eff = eff_lens[b];
    int base = t * 4;

    s_hist[t] = 0;
    if (t < NB + 1 - 1024) s_hist[1024 + t] = 0;
    if (t == 0) { s_hist[NB] = 0; s_ns = 0; }

    int4  sd4 = *(const int4*)  &sids [b * LL + base];
    float4 nz4 = *(const float4*)&noise[b * LL + base];
    int sm1 = (base >= 1) ? sids[b * LL + base - 1] : -1;
    int sm2 = (base >= 2) ? sids[b * LL + base - 2] : -1;
    __syncthreads();

    int   sd[6] = {sm2, sm1, sd4.x, sd4.y, sd4.z, sd4.w};
    float nz[4] = {nz4.x, nz4.y, nz4.z, nz4.w};

    unsigned long long key[4];
    int bid[4], slot[4];
    int nseg = 0;
#pragma unroll
    for (int i = 0; i < 4; i++) {
        int l = base + i;
        bool valid = l < eff;
        bool seg = valid && (sd[i + 2] != sd[i + 1]);
        bool fst = valid && (l >= 1) && (sd[i + 1] != sd[i]);
        nseg += seg ? 1 : 0;
        float v = (seg || fst) ? 0.0f : nz[i];
        unsigned int bits = __float_as_uint(v);
        key[i] = ((unsigned long long)bits << 12) | (unsigned)l;
        bid[i] = min(NB - 1, (int)(v * (float)NB));
        if (valid) slot[i] = atomicAdd(&s_hist[bid[i]], 1);
    }
    {
        int v = nseg;
#pragma unroll
        for (int d = 16; d > 0; d >>= 1) v += __shfl_down_sync(0xffffffffu, v, d);
        if (lane == 0 && v) atomicAdd(&s_ns, v);
    }
    __syncthreads();

    int ns = s_ns;
    int lk = 2 * ns + (int)((float)(eff - 2 * ns) * 0.25f);

    int c0 = s_hist[2 * t], c1 = s_hist[2 * t + 1];
    int ex = block_exscan(c0 + c1, s_wsum);
    s_hist[2 * t] = ex;
    s_hist[2 * t + 1] = ex + c0;
    if (t == 1023) s_hist[NB] = ex + c0 + c1;
    __syncthreads();

#pragma unroll
    for (int i = 0; i < 4; i++) {
        int l = base + i;
        if (l < eff) s_keys[s_hist[bid[i]] + slot[i]] = key[i];
    }
    __syncthreads();

    int r[4];
    bool kept[4];
    int cnt = 0;
#pragma unroll
    for (int i = 0; i < 4; i++) {
        int l = base + i;
        if (l < eff) {
            int lo = s_hist[bid[i]], hi = s_hist[bid[i] + 1];
            int c = 0;
            for (int m = lo; m < hi; m++) c += (s_keys[m] < key[i]) ? 1 : 0;
            r[i] = lo + c;
        } else {
            r[i] = l;
        }
        kept[i] = (l < eff) && (r[i] < lk);
        cnt += kept[i] ? 1 : 0;
    }
    __syncthreads();

    int p = block_exscan(cnt, s_wsum);

    const size_t O1 = (size_t)BB * LL * HH;
    const size_t O2 = O1 + (size_t)BB * LL;
    const size_t O3 = O2 + (size_t)BB * LL;
    float* mae = out + O1 + (size_t)b * LL;
    float* rst = out + O2 + (size_t)b * LL;
    float* unm = out + O3 + (size_t)b * LL;

#pragma unroll
    for (int i = 0; i < 4; i++) {
        int l = base + i;
        mae[l] = (l < eff && !kept[i]) ? 1.0f : 0.0f;
        rst[l] = (float)(kept[i] ? p : r[i]);
        if (kept[i]) {
            g_keptlist[b * LL + p] = l;
            unm[p] = (float)sd[i + 2];
            p++;
        }
        if (l >= lk) unm[l] = -1.0f;
    }
    if (t == 0) g_lenkeep[b] = lk;
}

// ---------------------------------------------------------------------------
// k_gemm: fused convert + mma.sync bf16 3-term GEMM + tail zeroing.
// Block (512 thr, 16 warps) = (batch, M-tile 128).  N=256 whole.
// 8 fp32 K-chunks of 64 cols.  A gathered via direct LDG -> regs -> converted
// into double-buffered A'hi/lo smem inside the MMA region; B' via double-
// buffered cp.async.  ONE sync per chunk.
// SMEM from 128-aligned base AB:
//   0: sBF[256]f  1024: sKL[128]i
//   2048:  A' buf x2 (each: hi 16K @+0, lo 16K @+16384) = 64 KB
//   67584: B' buf x2 (each: hi 32K @+0, lo 32K @+32768) = 128 KB
// ---------------------------------------------------------------------------
#define SM_AP 2048
#define SM_BP 67584
#define SMEMSZ (198656 + 1024)

__global__ void __launch_bounds__(512, 1)
k_gemm(const float* __restrict__ patches,
       const float* __restrict__ bias, const float* __restrict__ pos,
       float* __restrict__ out_seq) {
    extern __shared__ char dsm[];
    int b  = blockIdx.y;
    int p0 = blockIdx.x * 128;
    int lk = g_lenkeep[b];
    int t = threadIdx.x;

    // ---- pure-zero blocks: whole tile is tail (block-uniform branch) ----
    if (p0 >= lk) {
        float4* dst = (float4*)&out_seq[((size_t)b * LL + p0) * HH];
        float4 z = make_float4(0.f, 0.f, 0.f, 0.f);
#pragma unroll
        for (int i = 0; i < 16; i++) dst[t + i * 512] = z;
        return;
    }

    uint32_t AB = (smem_u32(dsm) + 127u) & ~127u;
    char* ABp = dsm + (AB - smem_u32(dsm));
    float* sBF = (float*)(ABp);
    int*   sKL = (int*)(ABp + 1024);

    int lane = t & 31, wid = t >> 5;
    int wm = wid & 3, wn = wid >> 2;

    if (t < 256) sBF[t] = bias[t] + g_fsemb[b * HH + t];
    if (t < 128) {
        int p = p0 + t;
        sKL[t] = (p < lk) ? g_keptlist[b * LL + p] : 0;
    }
    __syncthreads();   // sKL needed for LDG addresses

    // ---- A LDG mapping: row = t>>2, 16 f32 at col (t&3)*16 ----
    int cvr = t >> 2;
    int cvc = t & 3;
    const float* aPtr = &patches[((size_t)b * LL + sKL[cvr]) * PD + cvc * 16];
    // A' store: hi 2 STS.128 at swizzled segs {cvc*2, cvc*2+1} ^ (row&7); lo same
    uint32_t aStBase = (uint32_t)(SM_AP + cvr * 128);
    uint32_t aSeg0 = (uint32_t)(((cvc * 2)     ^ (cvr & 7)) * 16);
    uint32_t aSeg1 = (uint32_t)(((cvc * 2 + 1) ^ (cvr & 7)) * 16);

    // ---- B' cp addresses: 4096 segs (512 rows x 8 segs) / 512 -> 8 ----
    uint32_t bDst[8];
    int bSrcOff[8];
#pragma unroll
    for (int i = 0; i < 8; i++) {
        int sid = t + i * 512;
        int r = sid >> 3, s = sid & 7;
        bDst[i] = AB + SM_BP + (uint32_t)(r * 128 + ((s ^ (r & 7)) * 16));
        bSrcOff[i] = r * 64 + s * 8;
    }

    // ---- ldmatrix address components ----
    uint32_t aRB[2], aXP[2];
#pragma unroll
    for (int mt = 0; mt < 2; mt++) {
        int rowA = wm * 32 + mt * 16 + (lane & 15);
        aRB[mt] = AB + SM_AP + (uint32_t)(rowA * 128);
        aXP[mt] = (uint32_t)((rowA & 7) << 4);
    }
    uint32_t aSG = (uint32_t)((lane >> 4) * 16);
    uint32_t bRB[4], bXP[4];
#pragma unroll
    for (int g = 0; g < 4; g++) {
        int rowB = wn * 64 + g * 16 + ((lane >> 4) << 3) + (lane & 7);
        bRB[g] = AB + SM_BP + (uint32_t)(rowB * 128);
        bXP[g] = (uint32_t)((rowB & 7) << 4);
    }
    uint32_t bSG = (uint32_t)(((lane >> 3) & 1) * 16);

    float acc[2][8][4];
#pragma unroll
    for (int mt = 0; mt < 2; mt++)
#pragma unroll
        for (int nt = 0; nt < 8; nt++)
#pragma unroll
            for (int i = 0; i < 4; i++) acc[mt][nt][i] = 0.f;

    float4 av[4];

    auto cp_B = [&](int c) {
        uint32_t bb = (uint32_t)(c & 1) * 65536u;
        const __nv_bfloat16* Bg = &g_Bs[c * 32768];
#pragma unroll
        for (int i = 0; i < 8; i++) cp16(bDst[i] + bb, Bg + bSrcOff[i]);
        CP_COMMIT();
    };
    auto ldg_A = [&](int c) {
#pragma unroll
        for (int i = 0; i < 4; i++)
            av[i] = __ldg((const float4*)(aPtr + c * 64 + i * 4));
    };
    auto conv_A = [&](int c) {
        uint32_t hi[8], lo[8];
#pragma unroll
        for (int i = 0; i < 4; i++) {
            float4 v = av[i];
            __nv_bfloat162 h01 = __float22bfloat162_rn(make_float2(v.x, v.y));
            __nv_bfloat162 h23 = __float22bfloat162_rn(make_float2(v.z, v.w));
            float2 hf01 = __bfloat1622float2(h01);
            float2 hf23 = __bfloat1622float2(h23);
            __nv_bfloat162 l01 = __float22bfloat162_rn(make_float2(v.x - hf01.x, v.y - hf01.y));
            __nv_bfloat162 l23 = __float22bfloat162_rn(make_float2(v.z - hf23.x, v.w - hf23.y));
            hi[i * 2]     = *(uint32_t*)&h01;
            hi[i * 2 + 1] = *(uint32_t*)&h23;
            lo[i * 2]     = *(uint32_t*)&l01;
            lo[i * 2 + 1] = *(uint32_t*)&l23;
        }
        uint32_t base = aStBase + (uint32_t)(c & 1) * 32768u;
        *(uint4*)(ABp + base + aSeg0)         = make_uint4(hi[0], hi[1], hi[2], hi[3]);
        *(uint4*)(ABp + base + aSeg1)         = make_uint4(hi[4], hi[5], hi[6], hi[7]);
        *(uint4*)(ABp + base + 16384 + aSeg0) = make_uint4(lo[0], lo[1], lo[2], lo[3]);
        *(uint4*)(ABp + base + 16384 + aSeg1) = make_uint4(lo[4], lo[5], lo[6], lo[7]);
    };

    // ---- prologue: B'(0) in flight; convert A(0) ----
    cp_B(0);
    ldg_A(0);
    conv_A(0);
    asm volatile("cp.async.wait_group 0;" ::: "memory");
    __syncthreads();

    for (int c = 0; c < NCH; c++) {
        uint32_t ab = (uint32_t)(c & 1) * 32768u;
        uint32_t bb = (uint32_t)(c & 1) * 65536u;
        if (c + 1 < NCH) { cp_B(c + 1); ldg_A(c + 1); }

        // ---- MMA: 4 k16 stages x 3 terms; convert(c+1) inserted mid-stream ----
#pragma unroll
        for (int s = 0; s < 4; s++) {
            uint32_t ah[2][4], al[2][4], bf[4][4];
            uint32_t so = (uint32_t)(s * 32);
#pragma unroll
            for (int mt = 0; mt < 2; mt++) {
                uint32_t off = (so + aSG) ^ aXP[mt];
                ldsm4(ah[mt], aRB[mt] + ab + off);
                ldsm4(al[mt], aRB[mt] + ab + 16384u + off);
            }
#pragma unroll
            for (int g = 0; g < 4; g++)
                ldsm4(bf[g], bRB[g] + bb + ((so + bSG) ^ bXP[g]));
#pragma unroll
            for (int mt = 0; mt < 2; mt++)
#pragma unroll
                for (int nt = 0; nt < 8; nt++)
                    mma16816(acc[mt][nt], ah[mt],
                             bf[nt >> 1][(nt & 1) * 2], bf[nt >> 1][(nt & 1) * 2 + 1]);
            if (s == 0 && c + 1 < NCH) conv_A(c + 1);   // overlaps tensor work
#pragma unroll
            for (int mt = 0; mt < 2; mt++)
#pragma unroll
                for (int nt = 0; nt < 8; nt++)
                    mma16816(acc[mt][nt], al[mt],
                             bf[nt >> 1][(nt & 1) * 2], bf[nt >> 1][(nt & 1) * 2 + 1]);
#pragma unroll
            for (int g = 0; g < 4; g++)  // Blo region = +32768
                ldsm4(bf[g], bRB[g] + bb + 32768u + ((so + bSG) ^ bXP[g]));
#pragma unroll
            for (int mt = 0; mt < 2; mt++)
#pragma unroll
                for (int nt = 0; nt < 8; nt++)
                    mma16816(acc[mt][nt], ah[mt],
                             bf[nt >> 1][(nt & 1) * 2], bf[nt >> 1][(nt & 1) * 2 + 1]);
        }
        asm volatile("cp.async.wait_group 0;" ::: "memory");
        __syncthreads();
    }

    // ---- epilogue: acc + bias + fsemb + pos -> out; tail rows -> 0 ----
#pragma unroll
    for (int mt = 0; mt < 2; mt++) {
        int rbase = wm * 32 + mt * 16 + (lane >> 2);
#pragma unroll
        for (int h = 0; h < 2; h++) {
            int rr = rbase + h * 8;
            int p = p0 + rr;
            int kl = sKL[rr];
            bool ok = p < lk;
            float* orow = &out_seq[(((size_t)b * LL) + p) * HH];
            const float* prow = &pos[(size_t)kl * HH];
#pragma unroll
            for (int nt = 0; nt < 8; nt++) {
                int col = wn * 64 + nt * 8 + (lane & 3) * 2;
                float2 v;
                if (ok) {
                    v.x = acc[mt][nt][h * 2 + 0] + sBF[col]     + prow[col];
                    v.y = acc[mt][nt][h * 2 + 1] + sBF[col + 1] + prow[col + 1];
                } else {
                    v.x = 0.f; v.y = 0.f;
                }
                *(float2*)&orow[col] = v;
            }
        }
    }
}

// ---------------------------------------------------------------------------
extern "C" void kernel_launch(void* const* d_in, const int* in_sizes, int n_in,
                              void* d_out, int out_size) {
    const float* patches = (const float*)d_in[0];
    const int*   sids    = (const int*)  d_in[1];
    const int*   eff     = (const int*)  d_in[2];
    const float* noise   = (const float*)d_in[3];
    const float* fs      = (const float*)d_in[4];
    const float* W       = (const float*)d_in[5];
    const float* bias    = (const float*)d_in[6];
    const float* pos     = (const float*)d_in[7];
    const float* w1      = (const float*)d_in[8];
    const float* b1      = (const float*)d_in[9];
    const float* w2      = (const float*)d_in[10];
    const float* b2      = (const float*)d_in[11];
    float* out = (float*)d_out;

    cudaFuncSetAttribute(k_gemm, cudaFuncAttributeMaxDynamicSharedMemorySize, SMEMSZ);

    k_front<<<48, 1024>>>(sids, eff, noise, out, fs, w1, b1, w2, b2, W);
    k_gemm<<<dim3(32, BB), 512, SMEMSZ>>>(patches, bias, pos, out);

    (void)in_sizes; (void)n_in; (void)out_size;
}